// round 17
// baseline (speedup 1.0000x reference)
#include <cuda_runtime.h>
#include <cuda_bf16.h>
#include <cuda_fp16.h>
#include <mma.h>
#include <math.h>
#include <stdint.h>

using namespace nvcuda;

#define S_LEN 2048
#define D_MODEL 2048
#define N_H 16
#define N_KV 4
#define H_DIM 128
#define SCALING 0.08838834764831845f
#define DM0 0.9779029130879204f
#define KV_DIM (N_KV * H_DIM)
#define ALL_DIM 3072
#define ALL_XTILES 24

typedef __nv_bfloat16 bf16;
typedef __half fp16;

// fp32 scratch
__device__ float g_attn[(size_t)N_H * S_LEN * S_LEN];
__device__ float g_pp[2][(size_t)S_LEN * ALL_DIM];   // split-K partials

#define SZ_BIG  ((size_t)2048 * 2048)
#define SZ_SML  ((size_t)2048 * 512)
#define SZ_WALL ((size_t)3072 * 2048)
#define SZ_ATT  ((size_t)N_H * S_LEN * S_LEN)
__device__ bf16 g_qh[SZ_BIG],  g_ql[SZ_BIG];
__device__ bf16 g_kh[SZ_SML],  g_kl[SZ_SML];
__device__ fp16 g_hs16h[SZ_BIG], g_hs16l[SZ_BIG];
__device__ fp16 g_w16[SZ_WALL];
__device__ fp16 g_v16[SZ_SML];
__device__ fp16 g_at16[SZ_ATT];
__device__ fp16 g_c16[SZ_BIG];
__device__ fp16 g_wo16[SZ_BIG];

__device__ __forceinline__ void split_bf16(float v, bf16& hi, bf16& lo) {
    hi = __float2bfloat16_rn(v);
    lo = __float2bfloat16_rn(v - __bfloat162float(hi));
}
__device__ __forceinline__ uint32_t smem_u32(const void* p) {
    return (uint32_t)__cvta_generic_to_shared(p);
}
#define CP16(dst, src) asm volatile("cp.async.cg.shared.global [%0], [%1], 16;" :: "r"(dst), "l"(src))
#define CP_COMMIT()    asm volatile("cp.async.commit_group;" ::: "memory")
#define CP_WAIT1()     asm volatile("cp.async.wait_group 1;" ::: "memory")
#define CP_WAIT0()     asm volatile("cp.async.wait_group 0;" ::: "memory")

// ===========================================================================
// Fused input split
// ===========================================================================
#define SEG_HS  (2048 * 2048)
#define SEG_WQ  (2048 * 2048)
#define SEG_WK  (512 * 2048)
#define SEG_WV  (512 * 2048)
#define SEG_WO  (2048 * 2048)
#define SPLIT_TOTAL (SEG_HS + SEG_WQ + SEG_WK + SEG_WV + SEG_WO)

__global__ void split_all_kernel(const float* __restrict__ hs,
                                 const float* __restrict__ wq,
                                 const float* __restrict__ wk,
                                 const float* __restrict__ wv,
                                 const float* __restrict__ wo)
{
    int i = (blockIdx.x * blockDim.x + threadIdx.x) * 4;
    if (i >= SPLIT_TOTAL) return;

    const float* src;
    fp16* dstS = nullptr;
    fp16 *dH = nullptr, *dL = nullptr;
    int off;
    if (i < SEG_HS) {
        off = i; src = hs + off; dH = g_hs16h + off; dL = g_hs16l + off;
    } else if (i < SEG_HS + SEG_WQ) {
        off = i - SEG_HS; src = wq + off; dstS = g_w16 + off;
    } else if (i < SEG_HS + SEG_WQ + SEG_WK) {
        off = i - SEG_HS - SEG_WQ; src = wk + off; dstS = g_w16 + (size_t)2048 * 2048 + off;
    } else if (i < SEG_HS + SEG_WQ + SEG_WK + SEG_WV) {
        off = i - SEG_HS - SEG_WQ - SEG_WK; src = wv + off; dstS = g_w16 + (size_t)2560 * 2048 + off;
    } else {
        off = i - SEG_HS - SEG_WQ - SEG_WK - SEG_WV; src = wo + off; dstS = g_wo16 + off;
    }

    float4 v = *(const float4*)src;
    if (dstS) {
        __half2* H = (__half2*)dstS;
        H[0] = __halves2half2(__float2half_rn(v.x), __float2half_rn(v.y));
        H[1] = __halves2half2(__float2half_rn(v.z), __float2half_rn(v.w));
    } else {
        const float* p = (const float*)&v;
        fp16 h[4], l[4];
#pragma unroll
        for (int e = 0; e < 4; e++) {
            h[e] = __float2half_rn(p[e]);
            l[e] = __float2half_rn(p[e] - __half2float(h[e]));
        }
        __half2* H = (__half2*)dH;
        __half2* L = (__half2*)dL;
        H[0] = __halves2half2(h[0], h[1]); H[1] = __halves2half2(h[2], h[3]);
        L[0] = __halves2half2(l[0], l[1]); L[1] = __halves2half2(l[2], l[3]);
    }
}

// ===========================================================================
// fp16 2-product projection, split-K=2, fp32 partial output.
// ===========================================================================
#define PROJ_SMEM (2 * 30720)

__global__ void __launch_bounds__(128) fused_proj_kernel()
{
    extern __shared__ char smraw[];
    fp16* sm = (fp16*)smraw;
    const int x = blockIdx.x;
    const int mBase = blockIdx.y * 128;
    const int z = blockIdx.z;
    const int kOff = z * 1024;
    const int nBase = x * 128;
    float* C = g_pp[z];

    const int tid = threadIdx.x;
    const int warp = tid >> 5;
    const int wm = warp >> 1;
    const int wn = warp & 1;

    wmma::fragment<wmma::accumulator, 16, 16, 16, float> acc[4][4];
#pragma unroll
    for (int i = 0; i < 4; i++)
#pragma unroll
        for (int j = 0; j < 4; j++) wmma::fill_fragment(acc[i][j], 0.0f);

    const fp16* ApH = g_hs16h + (size_t)(mBase + tid) * D_MODEL + kOff;
    const fp16* ApL = g_hs16l + (size_t)(mBase + tid) * D_MODEL + kOff;
    const fp16* Bp  = g_w16  + (size_t)(nBase + tid) * D_MODEL + kOff;
    const uint32_t dbase = smem_u32(sm) + tid * 80;

    const int T = 1024 >> 5;

#define P_LOAD(buf, k0) do { \
        uint32_t d = dbase + (buf) * 30720; \
        CP16(d,          ApH + (k0));      CP16(d + 16,          ApH + (k0) + 8); \
        CP16(d + 32,     ApH + (k0) + 16); CP16(d + 48,          ApH + (k0) + 24); \
        CP16(d + 10240,      ApL + (k0));      CP16(d + 10240 + 16, ApL + (k0) + 8); \
        CP16(d + 10240 + 32, ApL + (k0) + 16); CP16(d + 10240 + 48, ApL + (k0) + 24); \
        CP16(d + 20480,      Bp + (k0));       CP16(d + 20480 + 16, Bp + (k0) + 8); \
        CP16(d + 20480 + 32, Bp + (k0) + 16);  CP16(d + 20480 + 48, Bp + (k0) + 24); \
        CP_COMMIT(); \
    } while (0)

    P_LOAD(0, 0);

#pragma unroll 1
    for (int t = 0; t < T; t++) {
        if (t + 1 < T) {
            P_LOAD((t + 1) & 1, (t + 1) * 32);
            CP_WAIT1();
        } else {
            CP_WAIT0();
        }
        __syncthreads();

        fp16* st   = sm + (t & 1) * 15360;
        fp16* Ah_s = st;
        fp16* Al_s = st + 5120;
        fp16* B_s  = st + 10240;
#pragma unroll
        for (int ks = 0; ks < 32; ks += 16) {
            wmma::fragment<wmma::matrix_b, 16, 16, 16, fp16, wmma::col_major> bf[4];
#pragma unroll
            for (int j = 0; j < 4; j++)
                wmma::load_matrix_sync(bf[j], &B_s[(wn * 64 + j * 16) * 40 + ks], 40);
#pragma unroll
            for (int i = 0; i < 4; i++) {
                wmma::fragment<wmma::matrix_a, 16, 16, 16, fp16, wmma::row_major> ah, al;
                wmma::load_matrix_sync(ah, &Ah_s[(wm * 64 + i * 16) * 40 + ks], 40);
                wmma::load_matrix_sync(al, &Al_s[(wm * 64 + i * 16) * 40 + ks], 40);
#pragma unroll
                for (int j = 0; j < 4; j++) {
                    wmma::mma_sync(acc[i][j], al, bf[j], acc[i][j]);
                    wmma::mma_sync(acc[i][j], ah, bf[j], acc[i][j]);
                }
            }
        }
        __syncthreads();
    }
#undef P_LOAD

#pragma unroll
    for (int i = 0; i < 4; i++)
#pragma unroll
        for (int j = 0; j < 4; j++)
            wmma::store_matrix_sync(
                C + (size_t)(mBase + wm * 64 + i * 16) * ALL_DIM + nBase + wn * 64 + j * 16,
                acc[i][j], ALL_DIM, wmma::mem_row_major);
}

// ===========================================================================
// Combine split-K partials + RoPE + split
// ===========================================================================
#define Q_PAIRS (S_LEN * N_H * 64)
#define K_PAIRS (S_LEN * N_KV * 64)
#define V_QUADS (S_LEN * KV_DIM / 4)
#define COMB_TOTAL (Q_PAIRS + K_PAIRS + V_QUADS)

__global__ void rope_combine_kernel(const float* __restrict__ cosb,
                                    const float* __restrict__ sinb)
{
    int idx = blockIdx.x * blockDim.x + threadIdx.x;
    if (idx >= COMB_TOTAL) return;

    const float* p0 = g_pp[0];
    const float* p1 = g_pp[1];

    if (idx < Q_PAIRS + K_PAIRS) {
        int nHeads, colBase;
        bf16 *hi, *lo;
        int li;
        if (idx < Q_PAIRS) { nHeads = N_H; colBase = 0; hi = g_qh; lo = g_ql; li = idx; }
        else { nHeads = N_KV; colBase = 2048; hi = g_kh; lo = g_kl; li = idx - Q_PAIRS; }
        int d = li & 63;
        int t = li >> 6;
        int hh = t % nHeads;
        int s  = t / nHeads;
        size_t src = (size_t)s * ALL_DIM + colBase + hh * H_DIM + d;
        float x1 = p0[src] + p1[src];
        float x2 = p0[src + 64] + p1[src + 64];
        float c1 = cosb[s * H_DIM + d];
        float s1 = sinb[s * H_DIM + d];
        float c2 = cosb[s * H_DIM + d + 64];
        float s2 = sinb[s * H_DIM + d + 64];
        float y1 = x1 * c1 - x2 * s1;
        float y2 = x2 * c2 + x1 * s2;
        size_t dst = (size_t)s * nHeads * H_DIM + (size_t)hh * H_DIM + d;
        bf16 h, l;
        split_bf16(y1, h, l); hi[dst] = h;      lo[dst] = l;
        split_bf16(y2, h, l); hi[dst + 64] = h; lo[dst + 64] = l;
    } else {
        int vq = idx - Q_PAIRS - K_PAIRS;
        int s = vq >> 7;
        int c4 = (vq & 127) * 4;
        size_t src = (size_t)s * ALL_DIM + 2560 + c4;
        float4 a = *(const float4*)(p0 + src);
        float4 b = *(const float4*)(p1 + src);
        float v0 = a.x + b.x, v1 = a.y + b.y, v2 = a.z + b.z, v3 = a.w + b.w;
        __half2* H = (__half2*)(g_v16 + (size_t)s * KV_DIM + c4);
        H[0] = __halves2half2(__float2half_rn(v0), __float2half_rn(v1));
        H[1] = __halves2half2(__float2half_rn(v2), __float2half_rn(v3));
    }
}

// ===========================================================================
// Scores: 3-product bf16, triangle-packed grid
// ===========================================================================
#define GEMM_SMEM (2 * 20480 * (int)sizeof(bf16))
#define TRI_TILES 136

__global__ void __launch_bounds__(128) scores_pre_kernel(float* __restrict__ attn)
{
    const int h = blockIdx.z;
    int p = blockIdx.x;
    int m = (int)((__fsqrt_rn(8.0f * p + 1.0f) - 1.0f) * 0.5f);
    while ((m + 1) * (m + 2) / 2 <= p) m++;
    while (m * (m + 1) / 2 > p) m--;
    const int mBase = m * 128;
    const int nBase = (p - m * (m + 1) / 2) * 128;

    extern __shared__ char smraw[];
    bf16* sm = (bf16*)smraw;
    const bf16* Ah = g_qh + h * H_DIM;
    const bf16* Al = g_ql + h * H_DIM;
    const bf16* Bh = g_kh + (h >> 2) * H_DIM;
    const bf16* Bl = g_kl + (h >> 2) * H_DIM;
    float* C = attn + (size_t)h * S_LEN * S_LEN;
    const int lda = N_H * H_DIM, ldb = KV_DIM, K = H_DIM, ldc = S_LEN;

    const int tid = threadIdx.x;
    const int warp = tid >> 5;
    const int wm = warp >> 1;
    const int wn = warp & 1;

    wmma::fragment<wmma::accumulator, 16, 16, 16, float> acc[4][4];
#pragma unroll
    for (int i = 0; i < 4; i++)
#pragma unroll
        for (int j = 0; j < 4; j++) wmma::fill_fragment(acc[i][j], 0.0f);

    const bf16* Ap_h = Ah + (size_t)(mBase + tid) * lda;
    const bf16* Ap_l = Al + (size_t)(mBase + tid) * lda;
    const bf16* Bp_h = Bh + (size_t)(nBase + tid) * ldb;
    const bf16* Bp_l = Bl + (size_t)(nBase + tid) * ldb;
    const uint32_t dbase = smem_u32(sm) + tid * 80;

    const int T = K >> 5;

#define LOAD_STAGE(buf, k0) do { \
        uint32_t d = dbase + (buf) * 40960; \
        CP16(d,          Ap_h + (k0));      CP16(d + 16,          Ap_h + (k0) + 8); \
        CP16(d + 32,     Ap_h + (k0) + 16); CP16(d + 48,          Ap_h + (k0) + 24); \
        CP16(d + 10240,      Ap_l + (k0));      CP16(d + 10240 + 16, Ap_l + (k0) + 8); \
        CP16(d + 10240 + 32, Ap_l + (k0) + 16); CP16(d + 10240 + 48, Ap_l + (k0) + 24); \
        CP16(d + 20480,      Bp_h + (k0));      CP16(d + 20480 + 16, Bp_h + (k0) + 8); \
        CP16(d + 20480 + 32, Bp_h + (k0) + 16); CP16(d + 20480 + 48, Bp_h + (k0) + 24); \
        CP16(d + 30720,      Bp_l + (k0));      CP16(d + 30720 + 16, Bp_l + (k0) + 8); \
        CP16(d + 30720 + 32, Bp_l + (k0) + 16); CP16(d + 30720 + 48, Bp_l + (k0) + 24); \
        CP_COMMIT(); \
    } while (0)

    LOAD_STAGE(0, 0);

#pragma unroll 1
    for (int t = 0; t < T; t++) {
        if (t + 1 < T) {
            LOAD_STAGE((t + 1) & 1, (t + 1) * 32);
            CP_WAIT1();
        } else {
            CP_WAIT0();
        }
        __syncthreads();

        bf16* st   = sm + (t & 1) * 20480;
        bf16* Ah_s = st;
        bf16* Al_s = st + 5120;
        bf16* Bh_s = st + 10240;
        bf16* Bl_s = st + 15360;
#pragma unroll
        for (int ks = 0; ks < 32; ks += 16) {
            wmma::fragment<wmma::matrix_b, 16, 16, 16, bf16, wmma::col_major> bh[4], bl[4];
#pragma unroll
            for (int j = 0; j < 4; j++) {
                wmma::load_matrix_sync(bh[j], &Bh_s[(wn * 64 + j * 16) * 40 + ks], 40);
                wmma::load_matrix_sync(bl[j], &Bl_s[(wn * 64 + j * 16) * 40 + ks], 40);
            }
#pragma unroll
            for (int i = 0; i < 4; i++) {
                wmma::fragment<wmma::matrix_a, 16, 16, 16, bf16, wmma::row_major> ah, al;
                wmma::load_matrix_sync(ah, &Ah_s[(wm * 64 + i * 16) * 40 + ks], 40);
                wmma::load_matrix_sync(al, &Al_s[(wm * 64 + i * 16) * 40 + ks], 40);
#pragma unroll
                for (int j = 0; j < 4; j++) {
                    wmma::mma_sync(acc[i][j], ah, bl[j], acc[i][j]);
                    wmma::mma_sync(acc[i][j], al, bh[j], acc[i][j]);
                    wmma::mma_sync(acc[i][j], ah, bh[j], acc[i][j]);
                }
            }
        }
        __syncthreads();
    }
#undef LOAD_STAGE

#pragma unroll
    for (int i = 0; i < 4; i++)
#pragma unroll
        for (int j = 0; j < 4; j++) {
#pragma unroll
            for (int t = 0; t < acc[i][j].num_elements; t++) acc[i][j].x[t] *= SCALING;
            wmma::store_matrix_sync(
                C + (size_t)(mBase + wm * 64 + i * 16) * ldc + nBase + wn * 64 + j * 16,
                acc[i][j], ldc, wmma::mem_row_major);
        }
}

// ===========================================================================
// wo GEMM: single fp16 product, fp32 accum/out.
// ===========================================================================
#define WO_STAGE 20480
#define WO_SMEM  (2 * WO_STAGE)

__global__ void __launch_bounds__(256) gemm_wo16_kernel(
    const fp16* __restrict__ A, const fp16* __restrict__ B,
    float* __restrict__ C, int K)
{
    extern __shared__ char smraw[];
    fp16* smh = (fp16*)smraw;
    const int tid = threadIdx.x;
    const int warp = tid >> 5;
    const int wm = warp & 3;
    const int wn = warp >> 2;
    const int mBase = blockIdx.y * 128;
    const int nBase = blockIdx.x * 128;

    wmma::fragment<wmma::accumulator, 16, 16, 16, float> acc[2][4];
#pragma unroll
    for (int i = 0; i < 2; i++)
#pragma unroll
        for (int j = 0; j < 4; j++) wmma::fill_fragment(acc[i][j], 0.0f);

    const int r  = tid >> 1;
    const int cc = (tid & 1) * 16;

    const fp16* Ap = A + (size_t)(mBase + r) * K + cc;
    const fp16* Bp = B + (size_t)(nBase + r) * K + cc;
    const uint32_t dbase = smem_u32(smh) + r * 80 + cc * 2;

    const int T = K >> 5;

#define WO_LOAD(buf, k0) do { \
        uint32_t d = dbase + (buf) * WO_STAGE; \
        CP16(d,          Ap + (k0)); CP16(d + 16,          Ap + (k0) + 8); \
        CP16(d + 10240,  Bp + (k0)); CP16(d + 10240 + 16,  Bp + (k0) + 8); \
        CP_COMMIT(); \
    } while (0)

    WO_LOAD(0, 0);

#pragma unroll 1
    for (int t = 0; t < T; t++) {
        if (t + 1 < T) {
            WO_LOAD((t + 1) & 1, (t + 1) * 32);
            CP_WAIT1();
        } else {
            CP_WAIT0();
        }
        __syncthreads();

        fp16* st  = smh + (t & 1) * (WO_STAGE / 2);
        fp16* A_s = st;
        fp16* B_s = st + 5120;
#pragma unroll
        for (int ks = 0; ks < 32; ks += 16) {
            wmma::fragment<wmma::matrix_b, 16, 16, 16, fp16, wmma::col_major> bf[4];
#pragma unroll
            for (int j = 0; j < 4; j++)
                wmma::load_matrix_sync(bf[j], &B_s[(wn * 64 + j * 16) * 40 + ks], 40);
            wmma::fragment<wmma::matrix_a, 16, 16, 16, fp16, wmma::row_major> af[2];
#pragma unroll
            for (int i = 0; i < 2; i++)
                wmma::load_matrix_sync(af[i], &A_s[(wm * 32 + i * 16) * 40 + ks], 40);
#pragma unroll
            for (int i = 0; i < 2; i++)
#pragma unroll
                for (int j = 0; j < 4; j++)
                    wmma::mma_sync(acc[i][j], af[i], bf[j], acc[i][j]);
        }
        __syncthreads();
    }
#undef WO_LOAD

#pragma unroll
    for (int i = 0; i < 2; i++)
#pragma unroll
        for (int j = 0; j < 4; j++)
            wmma::store_matrix_sync(
                C + (size_t)(mBase + wm * 32 + i * 16) * D_MODEL + nBase + wn * 64 + j * 16,
                acc[i][j], D_MODEL, wmma::mem_row_major);
}

// ===========================================================================
// entmax row (warp-collective, shfl only). Writes fp32 + fp16 within CH*32.
// ===========================================================================
template <int CH>
__device__ __forceinline__ void entmax_row_warp(float* __restrict__ x,
                                                fp16* __restrict__ xh,
                                                int n, int lane)
{
    float X[CH];
    float lmax = -INFINITY;
#pragma unroll
    for (int i = 0; i < CH; i++) {
        int j = lane + i * 32;
        if (j < n) {
            float v = x[j] * 0.5f;
            X[i] = v;
            lmax = fmaxf(lmax, v);
        } else {
            X[i] = -INFINITY;
        }
    }
#pragma unroll
    for (int o = 16; o > 0; o >>= 1) lmax = fmaxf(lmax, __shfl_xor_sync(0xffffffffu, lmax, o));

    float tau_lo = lmax - 1.0f;
    float dm = DM0;
    float tau_m = tau_lo;
#pragma unroll 1
    for (int it = 0; it < 32; it++) {
        dm *= 0.5f;
        tau_m = tau_lo + dm;
        float ls = 0.f;
#pragma unroll
        for (int i = 0; i < CH; i++) {
            float t = fmaxf(X[i] - tau_m, 0.f);
            ls = fmaf(t, t, ls);
        }
#pragma unroll
        for (int o = 16; o > 0; o >>= 1) ls += __shfl_xor_sync(0xffffffffu, ls, o);
        if (ls >= 1.0f) tau_lo = tau_m;
    }

    float ls = 0.f;
#pragma unroll
    for (int i = 0; i < CH; i++) {
        float t = fmaxf(X[i] - tau_m, 0.f);
        ls = fmaf(t, t, ls);
    }
#pragma unroll
    for (int o = 16; o > 0; o >>= 1) ls += __shfl_xor_sync(0xffffffffu, ls, o);
    float inv = 1.0f / ls;

#pragma unroll
    for (int i = 0; i < CH; i++) {
        int j = lane + i * 32;
        float t = fmaxf(X[i] - tau_m, 0.f);
        float v = (j < n) ? t * t * inv : 0.0f;
        x[j] = v;
        xh[j] = __float2half_rn(v);
    }
}

template <int CH>
__device__ __forceinline__ void entmax_rows16(float* __restrict__ xb,
                                              fp16* __restrict__ xhb,
                                              int mBase, int warp, int lane)
{
#pragma unroll 1
    for (int rr = 0; rr < 16; rr++) {
        int row = mBase + warp * 16 + rr;
        entmax_row_warp<CH>(xb + (size_t)row * S_LEN, xhb + (size_t)row * S_LEN,
                            row + 1, lane);
    }
}

// ===========================================================================
// FUSED entmax + attn@V kernel. grid (1, 16 mtiles (reversed), 16 heads).
// Phase 1: warp-per-row entmax over this CTA's 128 rows (+ fp32 tail zeros).
// Phase 2: GEMM ctx16 = at16 @ v16 over k < mBase+128.
// ===========================================================================
#define AV_STAGE 18944
#define AV_SMEM  (2 * AV_STAGE)

__global__ void __launch_bounds__(256) av_fused_kernel(float* __restrict__ attn)
{
    extern __shared__ char smraw[];
    fp16* smh = (fp16*)smraw;
    const int h = blockIdx.z;
    const int m = gridDim.y - 1 - blockIdx.y;   // heavy tiles first
    const int mBase = m * 128;

    const int tid = threadIdx.x;
    const int warp = tid >> 5;
    const int lane = tid & 31;

    float* xb = attn + (size_t)h * S_LEN * S_LEN;
    fp16*  xhb = g_at16 + (size_t)h * S_LEN * S_LEN;

    // ---- Phase 1: entmax on rows [mBase, mBase+128) ----
    switch (m) {
        case 0:  entmax_rows16<4>(xb, xhb, mBase, warp, lane); break;
        case 1:  entmax_rows16<8>(xb, xhb, mBase, warp, lane); break;
        case 2:  entmax_rows16<12>(xb, xhb, mBase, warp, lane); break;
        case 3:  entmax_rows16<16>(xb, xhb, mBase, warp, lane); break;
        case 4:  entmax_rows16<20>(xb, xhb, mBase, warp, lane); break;
        case 5:  entmax_rows16<24>(xb, xhb, mBase, warp, lane); break;
        case 6:  entmax_rows16<28>(xb, xhb, mBase, warp, lane); break;
        case 7:  entmax_rows16<32>(xb, xhb, mBase, warp, lane); break;
        case 8:  entmax_rows16<36>(xb, xhb, mBase, warp, lane); break;
        case 9:  entmax_rows16<40>(xb, xhb, mBase, warp, lane); break;
        case 10: entmax_rows16<44>(xb, xhb, mBase, warp, lane); break;
        case 11: entmax_rows16<48>(xb, xhb, mBase, warp, lane); break;
        case 12: entmax_rows16<52>(xb, xhb, mBase, warp, lane); break;
        case 13: entmax_rows16<56>(xb, xhb, mBase, warp, lane); break;
        case 14: entmax_rows16<60>(xb, xhb, mBase, warp, lane); break;
        default: entmax_rows16<64>(xb, xhb, mBase, warp, lane); break;
    }

    // fp32 tail zeros for columns [mBase+128, 2048)
    {
        const int tailStart = mBase + 128;
        const int tailVec = (S_LEN - tailStart) >> 2;
        const float4 z4 = make_float4(0.f, 0.f, 0.f, 0.f);
        if (tailVec > 0) {
            const int total = 128 * tailVec;
            for (int t = tid; t < total; t += 256) {
                int r = t / tailVec;
                int c = t - r * tailVec;
                *(float4*)(xb + (size_t)(mBase + r) * S_LEN + tailStart + c * 4) = z4;
            }
        }
    }
    __syncthreads();   // CTA-wide: gmem writes above visible to all threads below

    // ---- Phase 2: AV GEMM ----
    const int wm = warp & 3;
    const int wn = warp >> 2;

    const fp16* A_g = xhb;
    const fp16* B_g = g_v16 + (h >> 2) * H_DIM;

    const int rA = tid >> 1;
    const int cA = (tid & 1) * 16;
    const int rB = tid >> 3;
    const int cB = (tid & 7) * 16;

    const fp16* Ap = A_g + (size_t)(mBase + rA) * S_LEN + cA;
    const fp16* Bp = B_g + (size_t)rB * KV_DIM + cB;

    const uint32_t sb = smem_u32(smh);
    const uint32_t dA = sb + rA * 80 + cA * 2;
    const uint32_t dB = sb + 10240 + rB * 272 + cB * 2;

    wmma::fragment<wmma::accumulator, 16, 16, 16, float> acc[2][4];
#pragma unroll
    for (int i = 0; i < 2; i++)
#pragma unroll
        for (int j = 0; j < 4; j++) wmma::fill_fragment(acc[i][j], 0.0f);

    const int T = (mBase + 128) >> 5;

#define AV_LOAD(buf, k0) do { \
        uint32_t da = dA + (buf) * AV_STAGE; \
        CP16(da, Ap + (k0)); CP16(da + 16, Ap + (k0) + 8); \
        uint32_t db = dB + (buf) * AV_STAGE; \
        CP16(db, Bp + (size_t)(k0) * KV_DIM); CP16(db + 16, Bp + (size_t)(k0) * KV_DIM + 8); \
        CP_COMMIT(); \
    } while (0)

    AV_LOAD(0, 0);

#pragma unroll 1
    for (int t = 0; t < T; t++) {
        if (t + 1 < T) {
            AV_LOAD((t + 1) & 1, (t + 1) * 32);
            CP_WAIT1();
        } else {
            CP_WAIT0();
        }
        __syncthreads();

        fp16* st  = smh + (t & 1) * (AV_STAGE / 2);
        fp16* A_s = st;
        fp16* B_s = st + 5120;
#pragma unroll
        for (int ks = 0; ks < 32; ks += 16) {
            wmma::fragment<wmma::matrix_a, 16, 16, 16, fp16, wmma::row_major> af[2];
            wmma::fragment<wmma::matrix_b, 16, 16, 16, fp16, wmma::row_major> bf[4];
#pragma unroll
            for (int i = 0; i < 2; i++)
                wmma::load_matrix_sync(af[i], &A_s[(wm * 32 + i * 16) * 40 + ks], 40);
#pragma unroll
            for (int j = 0; j < 4; j++)
                wmma::load_matrix_sync(bf[j], &B_s[ks * 136 + wn * 64 + j * 16], 136);
#pragma unroll
            for (int i = 0; i < 2; i++)
#pragma unroll
                for (int j = 0; j < 4; j++)
                    wmma::mma_sync(acc[i][j], af[i], bf[j], acc[i][j]);
        }
        __syncthreads();
    }
#undef AV_LOAD

#pragma unroll
    for (int i = 0; i < 2; i++)
#pragma unroll
        for (int j = 0; j < 4; j++) {
            wmma::fragment<wmma::accumulator, 16, 16, 16, fp16> hacc;
#pragma unroll
            for (int t = 0; t < hacc.num_elements; t++)
                hacc.x[t] = __float2half_rn(acc[i][j].x[t]);
            wmma::store_matrix_sync(
                g_c16 + (size_t)(mBase + wm * 32 + i * 16) * (N_H * H_DIM)
                      + h * H_DIM + wn * 64 + j * 16,
                hacc, N_H * H_DIM, wmma::mem_row_major);
        }
}

// ===========================================================================
extern "C" void kernel_launch(void* const* d_in, const int* in_sizes, int n_in,
                              void* d_out, int out_size)
{
    const float* hs   = (const float*)d_in[0];
    const float* cosb = (const float*)d_in[1];
    const float* sinb = (const float*)d_in[2];
    const float* wq   = (const float*)d_in[3];
    const float* wk   = (const float*)d_in[4];
    const float* wv   = (const float*)d_in[5];
    const float* wo   = (const float*)d_in[6];
    float* out = (float*)d_out;

    float* ap;
    cudaGetSymbolAddress((void**)&ap, g_attn);

    fp16 *c16, *wo16;
    cudaGetSymbolAddress((void**)&c16, g_c16);
    cudaGetSymbolAddress((void**)&wo16, g_wo16);

    const size_t need = (size_t)S_LEN * D_MODEL + (size_t)N_H * S_LEN * S_LEN;
    float* attnBuf = ((size_t)out_size >= need) ? (out + (size_t)S_LEN * D_MODEL) : ap;

    cudaFuncSetAttribute(fused_proj_kernel, cudaFuncAttributeMaxDynamicSharedMemorySize, PROJ_SMEM);
    cudaFuncSetAttribute(scores_pre_kernel, cudaFuncAttributeMaxDynamicSharedMemorySize, GEMM_SMEM);
    cudaFuncSetAttribute(av_fused_kernel, cudaFuncAttributeMaxDynamicSharedMemorySize, AV_SMEM);
    cudaFuncSetAttribute(gemm_wo16_kernel, cudaFuncAttributeMaxDynamicSharedMemorySize, WO_SMEM);

    // 0) fused input splits
    split_all_kernel<<<(SPLIT_TOTAL / 4 + 255) / 256, 256>>>(hs, wq, wk, wv, wo);

    // 1) split-K=2 projection into partials
    fused_proj_kernel<<<dim3(ALL_XTILES, S_LEN / 128, 2), 128, PROJ_SMEM>>>();

    // 2) combine + RoPE + split
    rope_combine_kernel<<<(COMB_TOTAL + 255) / 256, 256>>>(cosb, sinb);

    // 3) causal scores (triangle-packed grid)
    scores_pre_kernel<<<dim3(TRI_TILES, 1, N_H), 128, GEMM_SMEM>>>(attnBuf);

    // 4+5) FUSED entmax + attn@V -> ctx16
    av_fused_kernel<<<dim3(1, S_LEN / 128, N_H), 256, AV_SMEM>>>(attnBuf);

    // 6) out = ctx16 @ wo16^T
    gemm_wo16_kernel<<<dim3(D_MODEL / 128, S_LEN / 128), 256, WO_SMEM>>>(
        c16, wo16, out, D_MODEL);
}